// round 13
// baseline (speedup 1.0000x reference)
#include <cuda_runtime.h>
#include <cstdint>

#define N_    32
#define CIN_  64
#define COUT_ 64
#define T_    6
#define V_    512
#define M_    (COUT_ * T_)      // 384 rows of the big GEMM (c*6+t)
#define NEG_FILL -1000.0f
#define SLOPE 0.2f

// Scratch (allocation-free rule: __device__ globals)
__device__ float g_xc[N_ * M_ * V_];   // tf32-rounded xc (GEMM A)
__device__ float g_ps[N_ * T_ * V_];
__device__ float g_pd[N_ * T_ * V_];
__device__ float g_si[N_ * V_];
__device__ float g_sj[N_ * V_];

__device__ __forceinline__ uint32_t f2tf32(float f) {
    uint32_t r;
    asm("cvt.rna.tf32.f32 %0, %1;" : "=r"(r) : "f"(f));
    return r;
}
__device__ __forceinline__ float f2tf32f(float f) { return __uint_as_float(f2tf32(f)); }

// ---------------------------------------------------------------------------
// Kernel A: conv + fused score partials. xc stored tf32-rounded (GEMM-only
// consumer); si/sj partials computed from EXACT fp32 acc first.
// ---------------------------------------------------------------------------
__global__ __launch_bounds__(256) void k_conv(const float* __restrict__ x,
                                              const float* __restrict__ w,
                                              const float* __restrict__ b,
                                              const float* __restrict__ l1_w) {
    __shared__ float xs[64][128];
    __shared__ float ws[64][64];
    const int n = blockIdx.z, t = blockIdx.y, bv = blockIdx.x * 128;
    const int tid = threadIdx.x;

#pragma unroll
    for (int r = 0; r < 4; ++r) {
        int f = tid + r * 256;
        int row = f >> 4, c4 = (f & 15) << 2;
        *(float4*)&ws[row][c4] = *(const float4*)(w + row * 64 + c4);
    }
#pragma unroll
    for (int r = 0; r < 8; ++r) {
        int f = tid + r * 256;
        int row = f >> 5, c4 = (f & 31) << 2;
        *(float4*)&xs[row][c4] =
            *(const float4*)(x + (((size_t)n * CIN_ + row) * T_ + t) * V_ + bv + c4);
    }
    __syncthreads();

    const int tx = tid & 31;
    const int ty = tid >> 5;
    float acc[8][4];
#pragma unroll
    for (int i = 0; i < 8; ++i)
#pragma unroll
        for (int j = 0; j < 4; ++j) acc[i][j] = 0.f;

#pragma unroll 4
    for (int kk = 0; kk < 64; ++kk) {
        float4 bx = *(float4*)&xs[kk][tx << 2];
#pragma unroll
        for (int cc = 0; cc < 8; ++cc) {
            float a = ws[ty * 8 + cc][kk];
            acc[cc][0] = fmaf(a, bx.x, acc[cc][0]);
            acc[cc][1] = fmaf(a, bx.y, acc[cc][1]);
            acc[cc][2] = fmaf(a, bx.z, acc[cc][2]);
            acc[cc][3] = fmaf(a, bx.w, acc[cc][3]);
        }
    }

    float ls[4] = {0.f, 0.f, 0.f, 0.f}, ld[4] = {0.f, 0.f, 0.f, 0.f};
#pragma unroll
    for (int cc = 0; cc < 8; ++cc) {
        int c = ty * 8 + cc;
        float bias = b[c];
        float wsrc = __ldg(l1_w + c);
        float wdst = __ldg(l1_w + COUT_ + c);
#pragma unroll
        for (int j = 0; j < 4; ++j) {
            acc[cc][j] += bias;
            ls[j] = fmaf(wsrc, acc[cc][j], ls[j]);
            ld[j] = fmaf(wdst, acc[cc][j], ld[j]);
        }
        *(float4*)(g_xc + (((size_t)n * COUT_ + c) * T_ + t) * V_ + bv + (tx << 2)) =
            make_float4(f2tf32f(acc[cc][0]), f2tf32f(acc[cc][1]),
                        f2tf32f(acc[cc][2]), f2tf32f(acc[cc][3]));
    }

    float* red = &xs[0][0];
    __syncthreads();
    *(float4*)&red[ty * 128 + tx * 4]        = make_float4(ls[0], ls[1], ls[2], ls[3]);
    *(float4*)&red[1024 + ty * 128 + tx * 4] = make_float4(ld[0], ld[1], ld[2], ld[3]);
    __syncthreads();

    {
        int sel = tid >> 7;
        int v = tid & 127;
        float s = 0.f;
#pragma unroll
        for (int r = 0; r < 8; ++r) s += red[sel * 1024 + r * 128 + v];
        float* dst = sel ? g_pd : g_ps;
        dst[((size_t)n * T_ + t) * V_ + bv + v] = s;
    }
}

// ---------------------------------------------------------------------------
// Kernel B': fold t-partials into si/sj.
// ---------------------------------------------------------------------------
__global__ __launch_bounds__(512) void k_finish(const float* __restrict__ l1_w,
                                                const float* __restrict__ l2_w,
                                                const float* __restrict__ l2_b) {
    const int n = blockIdx.x, v = threadIdx.x;
    float si = 0.f, sj = 0.f;
#pragma unroll
    for (int t = 0; t < T_; ++t) {
        float lw = __ldg(l2_w + t);
        si = fmaf(lw, g_ps[((size_t)n * T_ + t) * V_ + v], si);
        sj = fmaf(lw, g_pd[((size_t)n * T_ + t) * V_ + v], sj);
    }
    float ss = 0.f, sd = 0.f;
#pragma unroll
    for (int c = 0; c < COUT_; ++c) { ss += __ldg(l1_w + c); sd += __ldg(l1_w + COUT_ + c); }
    float lb = l2_b[0];
    g_si[n * V_ + v] = si + lb * ss;
    g_sj[n * V_ + v] = sj + lb * sd;
}

// ---------------------------------------------------------------------------
// Kernel C: softmax WITHOUT max subtraction (scores ~N(0,1), |s|<<88;
// masked = exp(-1000) = 0 exactly, matching reference semantics).
// One barrier total. Writes tf32-rounded a4 once into d_out.
// ---------------------------------------------------------------------------
__global__ __launch_bounds__(128) void k_softmax(const float* __restrict__ A,
                                                 const float* __restrict__ l1_b,
                                                 float* __restrict__ a4) {
    const int v = blockIdx.x, n = blockIdx.y, tid = threadIdx.x;
    const int lane = tid & 31, wrp = tid >> 5;
    __shared__ float red[4];

    const float siv = g_si[n * V_ + v] + l1_b[0];
    const float* mrow = A + (((size_t)n * 8 + 7) * V_ + v) * V_;
    const float* sjn = g_sj + n * V_;

    float4 sj4 = *(const float4*)(sjn + tid * 4);
    float4 mk4 = *(const float4*)(mrow + tid * 4);

    float s0 = siv + sj4.x, s1 = siv + sj4.y, s2 = siv + sj4.z, s3 = siv + sj4.w;
    s0 = s0 >= 0.f ? s0 : SLOPE * s0;
    s1 = s1 >= 0.f ? s1 : SLOPE * s1;
    s2 = s2 >= 0.f ? s2 : SLOPE * s2;
    s3 = s3 >= 0.f ? s3 : SLOPE * s3;

    float e0 = (mk4.x == 0.f) ? 0.f : __expf(s0);
    float e1 = (mk4.y == 0.f) ? 0.f : __expf(s1);
    float e2 = (mk4.z == 0.f) ? 0.f : __expf(s2);
    float e3 = (mk4.w == 0.f) ? 0.f : __expf(s3);

    float su = (e0 + e1) + (e2 + e3);
#pragma unroll
    for (int s = 16; s > 0; s >>= 1) su += __shfl_xor_sync(~0u, su, s);
    if (lane == 0) red[wrp] = su;
    __syncthreads();
    float inv = 1.0f / (((red[0] + red[1]) + (red[2] + red[3])));

    *(float4*)(a4 + ((size_t)n * V_ + v) * V_ + tid * 4) =
        make_float4(f2tf32f(e0 * inv), f2tf32f(e1 * inv),
                    f2tf32f(e2 * inv), f2tf32f(e3 * inv));
}

// ---------------------------------------------------------------------------
// Kernel D (mma.sync tf32 + 3-stage cp.async, unrolled x3): out = xc @ a4
// 128x128 tile, 8 warps (4M x 2N), warp tile 32x64, KC=32.
// Three smem stages with LITERAL stage offsets (chunks processed 3 at a
// time; 15 = 5x3 in loop + chunk 15 tail). ONE barrier per chunk:
//   wait_group 1 (stage c landed) -> syncthreads (visibility + all warps
//   past chunk c-1) -> prefetch c+2 into stage (c-1)%3 -> compute stage c%3.
// ---------------------------------------------------------------------------
#define BM 128
#define BN 128
#define KC 32
#define NCHUNK (V_ / KC)   // 16
#define PA 36
#define PB 136
#define SMA (BM * PA)
#define SMB (KC * PB)
#define STG (SMA + SMB)
#define SM_GEMM (3 * STG * 4)   // 107,520 B

#define CPA16(soff, gptr) \
    asm volatile("cp.async.ca.shared.global [%0], [%1], 16;" :: "r"(soff), "l"(gptr) : "memory")
#define CP_COMMIT() asm volatile("cp.async.commit_group;" ::: "memory")
#define CP_WAIT1()  asm volatile("cp.async.wait_group 1;" ::: "memory")
#define CP_WAIT0()  asm volatile("cp.async.wait_group 0;" ::: "memory")

__global__ __launch_bounds__(256) void k_gemm_mma(const float* __restrict__ A4,
                                                  float* __restrict__ OUT) {
    extern __shared__ float sm[];
    const uint32_t sb = (uint32_t)__cvta_generic_to_shared(sm);
    const int tid = threadIdx.x, wid = tid >> 5, lane = tid & 31;
    const int n = blockIdx.z, bm = blockIdx.y * BM, bn = blockIdx.x * BN;

    const float* Ap = g_xc + ((size_t)n * M_ + bm) * V_;   // [128][512] tf32
    const float* Bp = A4 + (size_t)n * V_ * V_ + bn;       // [512][128] tf32

    const int g = lane >> 2, tq = lane & 3;
    const int warpM = (wid & 3) * 32, warpN = (wid >> 2) * 64;

    float acc[2][8][4];
#pragma unroll
    for (int mt = 0; mt < 2; ++mt)
#pragma unroll
        for (int nt = 0; nt < 8; ++nt)
#pragma unroll
            for (int q = 0; q < 4; ++q) acc[mt][nt][q] = 0.f;

#define PREFETCH(kc, stage) do {                                                    \
    uint32_t asb = sb + ((stage) * STG) * 4;                                        \
    uint32_t bsb = asb + SMA * 4;                                                   \
    _Pragma("unroll")                                                               \
    for (int rr = 0; rr < 4; ++rr) {                                                \
        int idx = tid + rr * 256;                                                   \
        int arow = idx >> 3, ac4 = (idx & 7) * 4;                                   \
        CPA16(asb + (arow * PA + ac4) * 4,                                          \
              Ap + (size_t)arow * V_ + (kc) + ac4);                                 \
        int bk = idx >> 5, bc4 = (idx & 31) * 4;                                    \
        CPA16(bsb + (bk * PB + bc4) * 4,                                            \
              Bp + (size_t)((kc) + bk) * V_ + bc4);                                 \
    }                                                                               \
    CP_COMMIT();                                                                    \
} while (0)

#define COMPUTE(stage) do {                                                         \
    const float* Asb = sm + (stage) * STG;                                          \
    const float* Bsb = Asb + SMA;                                                   \
    _Pragma("unroll")                                                               \
    for (int ks = 0; ks < 4; ++ks) {                                                \
        const int k0 = ks * 8;                                                      \
        uint32_t a[2][4], b[8][2];                                                  \
        _Pragma("unroll")                                                           \
        for (int mt = 0; mt < 2; ++mt) {                                            \
            const float* base = Asb + (warpM + mt * 16 + g) * PA + k0 + tq;         \
            a[mt][0] = __float_as_uint(base[0]);                                    \
            a[mt][1] = __float_as_uint(base[8 * PA]);                               \
            a[mt][2] = __float_as_uint(base[4]);                                    \
            a[mt][3] = __float_as_uint(base[8 * PA + 4]);                           \
        }                                                                           \
        _Pragma("unroll")                                                           \
        for (int nt = 0; nt < 8; ++nt) {                                            \
            const float* base = Bsb + (k0 + tq) * PB + warpN + nt * 8 + g;          \
            b[nt][0] = __float_as_uint(base[0]);                                    \
            b[nt][1] = __float_as_uint(base[4 * PB]);                               \
        }                                                                           \
        _Pragma("unroll")                                                           \
        for (int mt = 0; mt < 2; ++mt)                                              \
            _Pragma("unroll")                                                       \
            for (int nt = 0; nt < 8; ++nt)                                          \
                asm volatile(                                                       \
                    "mma.sync.aligned.m16n8k8.row.col.f32.tf32.tf32.f32 "           \
                    "{%0,%1,%2,%3}, {%4,%5,%6,%7}, {%8,%9}, {%0,%1,%2,%3};"         \
                    : "+f"(acc[mt][nt][0]), "+f"(acc[mt][nt][1]),                   \
                      "+f"(acc[mt][nt][2]), "+f"(acc[mt][nt][3])                    \
                    : "r"(a[mt][0]), "r"(a[mt][1]), "r"(a[mt][2]), "r"(a[mt][3]),   \
                      "r"(b[nt][0]), "r"(b[nt][1]));                                \
    }                                                                               \
} while (0)

    PREFETCH(0, 0);
    PREFETCH(KC, 1);

    for (int cb = 0; cb < 15; cb += 3) {
        const int kc = cb * KC;
        // chunk cb (stage 0)
        CP_WAIT1();
        __syncthreads();
        PREFETCH(kc + 2 * KC, 2);
        COMPUTE(0);
        // chunk cb+1 (stage 1)
        CP_WAIT1();
        __syncthreads();
        PREFETCH(kc + 3 * KC, 0);
        COMPUTE(1);
        // chunk cb+2 (stage 2)
        CP_WAIT1();
        __syncthreads();
        if (cb < 12) PREFETCH(kc + 4 * KC, 1);
        COMPUTE(2);
    }
    // chunk 15 (stage 0)
    CP_WAIT0();
    __syncthreads();
    COMPUTE(0);

#pragma unroll
    for (int mt = 0; mt < 2; ++mt)
#pragma unroll
        for (int nt = 0; nt < 8; ++nt) {
            int row0 = bm + warpM + mt * 16 + g;
            int col = bn + warpN + nt * 8 + 2 * tq;
            float* o0 = OUT + ((size_t)n * M_ + row0) * V_ + col;
            *(float2*)o0 = make_float2(acc[mt][nt][0], acc[mt][nt][1]);
            float* o1 = o0 + 8 * V_;
            *(float2*)o1 = make_float2(acc[mt][nt][2], acc[mt][nt][3]);
        }
}

// ---------------------------------------------------------------------------
extern "C" void kernel_launch(void* const* d_in, const int* in_sizes, int n_in,
                              void* d_out, int out_size) {
    const float* x      = (const float*)d_in[0];
    const float* A      = (const float*)d_in[1];
    const float* conv_w = (const float*)d_in[2];
    const float* conv_b = (const float*)d_in[3];
    const float* l1_w   = (const float*)d_in[4];
    const float* l1_b   = (const float*)d_in[5];
    const float* l2_w   = (const float*)d_in[6];
    const float* l2_b   = (const float*)d_in[7];

    float* out = (float*)d_out;                       // (32,64,6,512)
    float* a4  = out + (size_t)N_ * COUT_ * T_ * V_;  // (32,1,512,512)

    cudaFuncSetAttribute(k_gemm_mma, cudaFuncAttributeMaxDynamicSharedMemorySize, SM_GEMM);

    k_conv<<<dim3(V_ / 128, T_, N_), 256>>>(x, conv_w, conv_b, l1_w);
    k_finish<<<N_, V_>>>(l1_w, l2_w, l2_b);
    k_softmax<<<dim3(V_, N_), 128>>>(A, l1_b, a4);
    k_gemm_mma<<<dim3(V_ / BN, M_ / BM, N_), 256, SM_GEMM>>>(a4, out);
}

// round 14
// speedup vs baseline: 1.1052x; 1.1052x over previous
#include <cuda_runtime.h>
#include <cstdint>

#define N_    32
#define CIN_  64
#define COUT_ 64
#define T_    6
#define V_    512
#define M_    (COUT_ * T_)      // 384 rows of the big GEMM (c*6+t)
#define NEG_FILL -1000.0f
#define SLOPE 0.2f

// Scratch (allocation-free rule: __device__ globals)
__device__ float g_xc[N_ * M_ * V_];   // tf32-rounded xc (GEMM A)
__device__ float g_ps[N_ * T_ * V_];
__device__ float g_pd[N_ * T_ * V_];
__device__ float g_si[N_ * V_];
__device__ float g_sj[N_ * V_];

__device__ __forceinline__ uint32_t f2tf32(float f) {
    uint32_t r;
    asm("cvt.rna.tf32.f32 %0, %1;" : "=r"(r) : "f"(f));
    return r;
}
__device__ __forceinline__ float f2tf32f(float f) { return __uint_as_float(f2tf32(f)); }

// ---------------------------------------------------------------------------
// Kernel A: conv + fused score partials. xc stored tf32-rounded (GEMM-only
// consumer); si/sj partials computed from EXACT fp32 acc first.
// ---------------------------------------------------------------------------
__global__ __launch_bounds__(256) void k_conv(const float* __restrict__ x,
                                              const float* __restrict__ w,
                                              const float* __restrict__ b,
                                              const float* __restrict__ l1_w) {
    __shared__ float xs[64][128];
    __shared__ float ws[64][64];
    const int n = blockIdx.z, t = blockIdx.y, bv = blockIdx.x * 128;
    const int tid = threadIdx.x;

#pragma unroll
    for (int r = 0; r < 4; ++r) {
        int f = tid + r * 256;
        int row = f >> 4, c4 = (f & 15) << 2;
        *(float4*)&ws[row][c4] = *(const float4*)(w + row * 64 + c4);
    }
#pragma unroll
    for (int r = 0; r < 8; ++r) {
        int f = tid + r * 256;
        int row = f >> 5, c4 = (f & 31) << 2;
        *(float4*)&xs[row][c4] =
            *(const float4*)(x + (((size_t)n * CIN_ + row) * T_ + t) * V_ + bv + c4);
    }
    __syncthreads();

    const int tx = tid & 31;
    const int ty = tid >> 5;
    float acc[8][4];
#pragma unroll
    for (int i = 0; i < 8; ++i)
#pragma unroll
        for (int j = 0; j < 4; ++j) acc[i][j] = 0.f;

#pragma unroll 4
    for (int kk = 0; kk < 64; ++kk) {
        float4 bx = *(float4*)&xs[kk][tx << 2];
#pragma unroll
        for (int cc = 0; cc < 8; ++cc) {
            float a = ws[ty * 8 + cc][kk];
            acc[cc][0] = fmaf(a, bx.x, acc[cc][0]);
            acc[cc][1] = fmaf(a, bx.y, acc[cc][1]);
            acc[cc][2] = fmaf(a, bx.z, acc[cc][2]);
            acc[cc][3] = fmaf(a, bx.w, acc[cc][3]);
        }
    }

    float ls[4] = {0.f, 0.f, 0.f, 0.f}, ld[4] = {0.f, 0.f, 0.f, 0.f};
#pragma unroll
    for (int cc = 0; cc < 8; ++cc) {
        int c = ty * 8 + cc;
        float bias = b[c];
        float wsrc = __ldg(l1_w + c);
        float wdst = __ldg(l1_w + COUT_ + c);
#pragma unroll
        for (int j = 0; j < 4; ++j) {
            acc[cc][j] += bias;
            ls[j] = fmaf(wsrc, acc[cc][j], ls[j]);
            ld[j] = fmaf(wdst, acc[cc][j], ld[j]);
        }
        *(float4*)(g_xc + (((size_t)n * COUT_ + c) * T_ + t) * V_ + bv + (tx << 2)) =
            make_float4(f2tf32f(acc[cc][0]), f2tf32f(acc[cc][1]),
                        f2tf32f(acc[cc][2]), f2tf32f(acc[cc][3]));
    }

    float* red = &xs[0][0];
    __syncthreads();
    *(float4*)&red[ty * 128 + tx * 4]        = make_float4(ls[0], ls[1], ls[2], ls[3]);
    *(float4*)&red[1024 + ty * 128 + tx * 4] = make_float4(ld[0], ld[1], ld[2], ld[3]);
    __syncthreads();

    {
        int sel = tid >> 7;
        int v = tid & 127;
        float s = 0.f;
#pragma unroll
        for (int r = 0; r < 8; ++r) s += red[sel * 1024 + r * 128 + v];
        float* dst = sel ? g_pd : g_ps;
        dst[((size_t)n * T_ + t) * V_ + bv + v] = s;
    }
}

// ---------------------------------------------------------------------------
// Kernel B': fold t-partials into si/sj.
// ---------------------------------------------------------------------------
__global__ __launch_bounds__(512) void k_finish(const float* __restrict__ l1_w,
                                                const float* __restrict__ l2_w,
                                                const float* __restrict__ l2_b) {
    const int n = blockIdx.x, v = threadIdx.x;
    float si = 0.f, sj = 0.f;
#pragma unroll
    for (int t = 0; t < T_; ++t) {
        float lw = __ldg(l2_w + t);
        si = fmaf(lw, g_ps[((size_t)n * T_ + t) * V_ + v], si);
        sj = fmaf(lw, g_pd[((size_t)n * T_ + t) * V_ + v], sj);
    }
    float ss = 0.f, sd = 0.f;
#pragma unroll
    for (int c = 0; c < COUT_; ++c) { ss += __ldg(l1_w + c); sd += __ldg(l1_w + COUT_ + c); }
    float lb = l2_b[0];
    g_si[n * V_ + v] = si + lb * ss;
    g_sj[n * V_ + v] = sj + lb * sd;
}

// ---------------------------------------------------------------------------
// Kernel C: softmax, WARP-PER-ROW. 256 threads = 8 warps = 8 rows (same n),
// zero __syncthreads. No max-subtraction (|scores| << 88; masked entries
// produce exp->0 exactly as reference). Lane covers cols q*128 + lane*4
// (fully coalesced). Writes tf32-rounded a4 once into d_out.
// ---------------------------------------------------------------------------
__global__ __launch_bounds__(256) void k_softmax(const float* __restrict__ A,
                                                 const float* __restrict__ l1_b,
                                                 float* __restrict__ a4) {
    const int n = blockIdx.y;
    const int v = blockIdx.x * 8 + (threadIdx.x >> 5);
    const int lane = threadIdx.x & 31;

    const float siv = g_si[n * V_ + v] + l1_b[0];
    const float* mrow = A + (((size_t)n * 8 + 7) * V_ + v) * V_ + lane * 4;
    const float* sjn = g_sj + n * V_ + lane * 4;

    float e[16];
    float su = 0.f;
#pragma unroll
    for (int q = 0; q < 4; ++q) {
        float4 s4 = *(const float4*)(sjn + q * 128);
        float4 m4 = *(const float4*)(mrow + q * 128);
        float s0 = siv + s4.x, s1 = siv + s4.y, s2 = siv + s4.z, s3 = siv + s4.w;
        s0 = s0 >= 0.f ? s0 : SLOPE * s0;
        s1 = s1 >= 0.f ? s1 : SLOPE * s1;
        s2 = s2 >= 0.f ? s2 : SLOPE * s2;
        s3 = s3 >= 0.f ? s3 : SLOPE * s3;
        e[q * 4 + 0] = (m4.x == 0.f) ? 0.f : __expf(s0);
        e[q * 4 + 1] = (m4.y == 0.f) ? 0.f : __expf(s1);
        e[q * 4 + 2] = (m4.z == 0.f) ? 0.f : __expf(s2);
        e[q * 4 + 3] = (m4.w == 0.f) ? 0.f : __expf(s3);
        su += (e[q * 4 + 0] + e[q * 4 + 1]) + (e[q * 4 + 2] + e[q * 4 + 3]);
    }

#pragma unroll
    for (int s = 16; s > 0; s >>= 1) su += __shfl_xor_sync(~0u, su, s);
    float inv = 1.0f / su;

    float* orow = a4 + ((size_t)n * V_ + v) * V_ + lane * 4;
#pragma unroll
    for (int q = 0; q < 4; ++q)
        *(float4*)(orow + q * 128) =
            make_float4(f2tf32f(e[q * 4 + 0] * inv), f2tf32f(e[q * 4 + 1] * inv),
                        f2tf32f(e[q * 4 + 2] * inv), f2tf32f(e[q * 4 + 3] * inv));
}

// ---------------------------------------------------------------------------
// Kernel D (mma.sync tf32 + 2-stage cp.async): out[n] (384x512) = xc @ a4
// EXACT R12 structure (best measured: 53.3us).
// ---------------------------------------------------------------------------
#define BM 128
#define BN 128
#define KC 32
#define NCHUNK (V_ / KC)   // 16
#define PA 36
#define PB 136
#define SMA (BM * PA)
#define SMB (KC * PB)
#define SM_GEMM ((2 * SMA + 2 * SMB) * 4)   // 71,680 B

#define CPA16(soff, gptr) \
    asm volatile("cp.async.ca.shared.global [%0], [%1], 16;" :: "r"(soff), "l"(gptr) : "memory")
#define CP_COMMIT() asm volatile("cp.async.commit_group;" ::: "memory")

__global__ __launch_bounds__(256) void k_gemm_mma(const float* __restrict__ A4,
                                                  float* __restrict__ OUT) {
    extern __shared__ float sm[];
    const uint32_t sb = (uint32_t)__cvta_generic_to_shared(sm);
    const int tid = threadIdx.x, wid = tid >> 5, lane = tid & 31;
    const int n = blockIdx.z, bm = blockIdx.y * BM, bn = blockIdx.x * BN;

    const float* Ap = g_xc + ((size_t)n * M_ + bm) * V_;   // [128][512] tf32
    const float* Bp = A4 + (size_t)n * V_ * V_ + bn;       // [512][128] tf32

    const int g = lane >> 2, tq = lane & 3;
    const int warpM = (wid & 3) * 32, warpN = (wid >> 2) * 64;

    float acc[2][8][4];
#pragma unroll
    for (int mt = 0; mt < 2; ++mt)
#pragma unroll
        for (int nt = 0; nt < 8; ++nt)
#pragma unroll
            for (int q = 0; q < 4; ++q) acc[mt][nt][q] = 0.f;

#define PREFETCH(kc, buf) do {                                                      \
    uint32_t asb = sb + ((buf) * SMA) * 4;                                          \
    uint32_t bsb = sb + ((2 * SMA + (buf) * SMB)) * 4;                              \
    _Pragma("unroll")                                                               \
    for (int rr = 0; rr < 4; ++rr) {                                                \
        int idx = tid + rr * 256;                                                   \
        int arow = idx >> 3, ac4 = (idx & 7) * 4;                                   \
        CPA16(asb + (arow * PA + ac4) * 4,                                          \
              Ap + (size_t)arow * V_ + (kc) + ac4);                                 \
        int bk = idx >> 5, bc4 = (idx & 31) * 4;                                    \
        CPA16(bsb + (bk * PB + bc4) * 4,                                            \
              Bp + (size_t)((kc) + bk) * V_ + bc4);                                 \
    }                                                                               \
} while (0)

    PREFETCH(0, 0);
    CP_COMMIT();

    int buf = 0;
    for (int c = 0; c < NCHUNK; ++c) {
        const bool more = (c + 1) < NCHUNK;
        if (more) {
            PREFETCH((c + 1) * KC, buf ^ 1);
            CP_COMMIT();
            asm volatile("cp.async.wait_group 1;" ::: "memory");
        } else {
            asm volatile("cp.async.wait_group 0;" ::: "memory");
        }
        __syncthreads();

        const float* Asb = sm + buf * SMA;
        const float* Bsb = sm + 2 * SMA + buf * SMB;
#pragma unroll
        for (int ks = 0; ks < 4; ++ks) {
            const int k0 = ks * 8;
            uint32_t a[2][4], b[8][2];
#pragma unroll
            for (int mt = 0; mt < 2; ++mt) {
                const float* base = Asb + (warpM + mt * 16 + g) * PA + k0 + tq;
                a[mt][0] = __float_as_uint(base[0]);
                a[mt][1] = __float_as_uint(base[8 * PA]);
                a[mt][2] = __float_as_uint(base[4]);
                a[mt][3] = __float_as_uint(base[8 * PA + 4]);
            }
#pragma unroll
            for (int nt = 0; nt < 8; ++nt) {
                const float* base = Bsb + (k0 + tq) * PB + warpN + nt * 8 + g;
                b[nt][0] = __float_as_uint(base[0]);
                b[nt][1] = __float_as_uint(base[4 * PB]);
            }
#pragma unroll
            for (int mt = 0; mt < 2; ++mt)
#pragma unroll
                for (int nt = 0; nt < 8; ++nt)
                    asm volatile(
                        "mma.sync.aligned.m16n8k8.row.col.f32.tf32.tf32.f32 "
                        "{%0,%1,%2,%3}, {%4,%5,%6,%7}, {%8,%9}, {%0,%1,%2,%3};"
                        : "+f"(acc[mt][nt][0]), "+f"(acc[mt][nt][1]),
                          "+f"(acc[mt][nt][2]), "+f"(acc[mt][nt][3])
                        : "r"(a[mt][0]), "r"(a[mt][1]), "r"(a[mt][2]), "r"(a[mt][3]),
                          "r"(b[nt][0]), "r"(b[nt][1]));
        }
        __syncthreads();
        buf ^= 1;
    }

#pragma unroll
    for (int mt = 0; mt < 2; ++mt)
#pragma unroll
        for (int nt = 0; nt < 8; ++nt) {
            int row0 = bm + warpM + mt * 16 + g;
            int col = bn + warpN + nt * 8 + 2 * tq;
            float* o0 = OUT + ((size_t)n * M_ + row0) * V_ + col;
            *(float2*)o0 = make_float2(acc[mt][nt][0], acc[mt][nt][1]);
            float* o1 = o0 + 8 * V_;
            *(float2*)o1 = make_float2(acc[mt][nt][2], acc[mt][nt][3]);
        }
}

// ---------------------------------------------------------------------------
extern "C" void kernel_launch(void* const* d_in, const int* in_sizes, int n_in,
                              void* d_out, int out_size) {
    const float* x      = (const float*)d_in[0];
    const float* A      = (const float*)d_in[1];
    const float* conv_w = (const float*)d_in[2];
    const float* conv_b = (const float*)d_in[3];
    const float* l1_w   = (const float*)d_in[4];
    const float* l1_b   = (const float*)d_in[5];
    const float* l2_w   = (const float*)d_in[6];
    const float* l2_b   = (const float*)d_in[7];

    float* out = (float*)d_out;                       // (32,64,6,512)
    float* a4  = out + (size_t)N_ * COUT_ * T_ * V_;  // (32,1,512,512)

    cudaFuncSetAttribute(k_gemm_mma, cudaFuncAttributeMaxDynamicSharedMemorySize, SM_GEMM);

    k_conv<<<dim3(V_ / 128, T_, N_), 256>>>(x, conv_w, conv_b, l1_w);
    k_finish<<<N_, V_>>>(l1_w, l2_w, l2_b);
    k_softmax<<<dim3(V_ / 8, N_), 256>>>(A, l1_b, a4);
    k_gemm_mma<<<dim3(V_ / BN, M_ / BM, N_), 256, SM_GEMM>>>(a4, out);
}